// round 15
// baseline (speedup 1.0000x reference)
#include <cuda_runtime.h>
#include <cuda_bf16.h>
#include <cuda_fp16.h>
#include <cstdint>

#define B_  4
#define S_  2048
#define DE  1024
#define DC  768
#define NH  16
#define DH  64
#define M_  (B_ * S_)   // 8192

// ---------------- scratch (allocation-free) ----------------
__device__ __half g_xf[M_ * DE];
__device__ __half g_yf[M_ * DC];
__device__ __half g_of[M_ * DE];      // attention output (single fp16)
// fp16 attention operands (Q single, K/V split)
__device__ __half g_Qf[M_ * DE];
__device__ __half g_Kh[M_ * DE], g_Kl[M_ * DE];
__device__ __half g_Vh[M_ * DE], g_Vl[M_ * DE];
// fp16 split transposed weights, [N, K] K-major
__device__ __half g_wqh[DE * DE], g_wql[DE * DE];
__device__ __half g_wkh[DE * DC], g_wkl[DE * DC];
__device__ __half g_wvh[DE * DC], g_wvl[DE * DC];
__device__ __half g_woh[DE * DE], g_wol[DE * DE];

// ---------------- helpers ----------------
__device__ __forceinline__ uint32_t s2u(const void* p) {
    uint32_t a;
    asm("{ .reg .u64 t; cvta.to.shared.u64 t, %1; cvt.u32.u64 %0, t; }"
        : "=r"(a) : "l"(p));
    return a;
}
__device__ __forceinline__ void cp16(uint32_t saddr, const void* g) {
    asm volatile("cp.async.cg.shared.global [%0], [%1], 16;" :: "r"(saddr), "l"(g));
}
__device__ __forceinline__ void ldsm4(uint32_t* r, uint32_t addr) {
    asm volatile("ldmatrix.sync.aligned.m8n8.x4.shared.b16 {%0,%1,%2,%3}, [%4];"
        : "=r"(r[0]), "=r"(r[1]), "=r"(r[2]), "=r"(r[3]) : "r"(addr));
}
__device__ __forceinline__ void ldsm4t(uint32_t* r, uint32_t addr) {
    asm volatile("ldmatrix.sync.aligned.m8n8.x4.trans.shared.b16 {%0,%1,%2,%3}, [%4];"
        : "=r"(r[0]), "=r"(r[1]), "=r"(r[2]), "=r"(r[3]) : "r"(addr));
}
__device__ __forceinline__ void mma_fp16(float* c, const uint32_t* a,
                                         uint32_t b0, uint32_t b1) {
    asm volatile(
        "mma.sync.aligned.m16n8k16.row.col.f32.f16.f16.f32 "
        "{%0,%1,%2,%3}, {%4,%5,%6,%7}, {%8,%9}, {%0,%1,%2,%3};"
        : "+f"(c[0]), "+f"(c[1]), "+f"(c[2]), "+f"(c[3])
        : "r"(a[0]), "r"(a[1]), "r"(a[2]), "r"(a[3]), "r"(b0), "r"(b1));
}
// split-pack two floats -> fp16 hi pair (ret) + lo pair (out)
__device__ __forceinline__ uint32_t packsplit16(float a, float b, uint32_t& lo) {
    __half ha = __float2half_rn(a), hb = __float2half_rn(b);
    __half la = __float2half_rn(a - __half2float(ha));
    __half lb = __float2half_rn(b - __half2float(hb));
    __half2 H(ha, hb), L(la, lb);
    lo = *(uint32_t*)&L;
    return *(uint32_t*)&H;
}

// ---------------------------------------------------------------------------
// f32 -> fp16 single
// ---------------------------------------------------------------------------
__global__ __launch_bounds__(256)
void conv_f16(const float* __restrict__ in, __half* __restrict__ out, int n4)
{
    int i = blockIdx.x * 256 + threadIdx.x;
    if (i >= n4) return;
    float4 v = ((const float4*)in)[i];
    __half2 h0 = __floats2half2_rn(v.x, v.y);
    __half2 h1 = __floats2half2_rn(v.z, v.w);
    ((__half2*)out)[i * 2 + 0] = h0;
    ((__half2*)out)[i * 2 + 1] = h1;
}

// ---------------------------------------------------------------------------
// transpose + split: W[K,N] f32 -> Wt_hi/Wt_lo [N,K] fp16
// ---------------------------------------------------------------------------
__global__ __launch_bounds__(256)
void tsplit_w16(const float* __restrict__ W, __half* __restrict__ hi,
                __half* __restrict__ lo, int K, int N)
{
    __shared__ float t[32][33];
    int tx = threadIdx.x & 31, ty = threadIdx.x >> 5;
    int n0 = blockIdx.x * 32, k0 = blockIdx.y * 32;
#pragma unroll
    for (int j = 0; j < 32; j += 8)
        t[ty + j][tx] = W[(size_t)(k0 + ty + j) * N + n0 + tx];
    __syncthreads();
#pragma unroll
    for (int j = 0; j < 32; j += 8) {
        float v = t[tx][ty + j];
        __half h = __float2half_rn(v);
        size_t o = (size_t)(n0 + ty + j) * K + k0 + tx;
        hi[o] = h;
        lo[o] = __float2half_rn(v - __half2float(h));
    }
}

// ---------------------------------------------------------------------------
// fp16 one-sided-split HMMA GEMM: 128x128 tile, BK=32, 2 CTA/SM,
// *** 3-stage cp.async pipeline (2-deep prefetch, wait_group 1) ***
// C = A16[M,K] @ (Wh+Wl)[N,K]^T + bias, * scale. 2 MMAs per k16.
// ---------------------------------------------------------------------------
#define TSTR   40
#define TILEB  (128 * TSTR * 2)        // 10240 B
#define STAGEB (3 * TILEB)             // 30720 B (A, Bh, Bl)
#define GSMEM  (3 * STAGEB)            // 92160 B (3 stages)

__device__ __forceinline__ void load_stage(
    uint32_t stb, const __half* A, const __half* Bh, const __half* Bl,
    int bm, int bn, int k0, int K, int tid)
{
    const int r  = tid >> 1;
    const int s0 = (tid & 1) * 2;
    const uint32_t so = (uint32_t)(r * (TSTR * 2) + s0 * 16);
    const size_t ga = (size_t)(bm + r) * K + k0 + s0 * 8;
    const size_t gb = (size_t)(bn + r) * K + k0 + s0 * 8;
    cp16(stb + so,                  A  + ga);
    cp16(stb + so + 16,             A  + ga + 8);
    cp16(stb + TILEB + so,          Bh + gb);
    cp16(stb + TILEB + so + 16,     Bh + gb + 8);
    cp16(stb + 2 * TILEB + so,      Bl + gb);
    cp16(stb + 2 * TILEB + so + 16, Bl + gb + 8);
    asm volatile("cp.async.commit_group;" ::: "memory");
}

__device__ __forceinline__ void gemm_body(
    const __half* __restrict__ A,
    const __half* __restrict__ Bh, const __half* __restrict__ Bl,
    const float* __restrict__ bias, float* __restrict__ Cf,
    __half* __restrict__ Ch, __half* __restrict__ Cl, __half* __restrict__ Cq,
    float scale, int N, int K, char* smem)
{
    const uint32_t sb = s2u(smem);
    const int tid  = threadIdx.x;
    const int lane = tid & 31;
    const int wid  = tid >> 5;
    const int wm   = wid >> 2;
    const int wn   = wid & 3;
    const int bm = blockIdx.y * 128, bn = blockIdx.x * 128;
    const int NC = K / 32;

    float acc[4][4][4];
#pragma unroll
    for (int i = 0; i < 4; i++)
#pragma unroll
        for (int j = 0; j < 4; j++)
#pragma unroll
            for (int q = 0; q < 4; q++) acc[i][j][q] = 0.0f;

    const uint32_t aRow = (uint32_t)(wm * 64 + (lane & 15));
    const uint32_t aCol = (uint32_t)(8 * (lane >> 4));
    const uint32_t bRow = (uint32_t)(wn * 32 + (lane & 7) + 8 * (lane >> 4));
    const uint32_t bCol = (uint32_t)(8 * ((lane >> 3) & 1));

    // Prologue: 2-deep prefetch
    load_stage(sb,          A, Bh, Bl, bm, bn, 0,  K, tid);
    load_stage(sb + STAGEB, A, Bh, Bl, bm, bn, 32, K, tid);

    int buf = 0;
    for (int c = 0; c < NC; c++) {
        // stage c must be complete; stage c+1 may stay in flight
        if (c + 1 < NC) asm volatile("cp.async.wait_group 1;" ::: "memory");
        else            asm volatile("cp.async.wait_group 0;" ::: "memory");
        __syncthreads();

        if (c + 2 < NC) {
            int nbuf = buf + 2; if (nbuf >= 3) nbuf -= 3;
            load_stage(sb + nbuf * STAGEB, A, Bh, Bl, bm, bn, (c + 2) * 32, K, tid);
        }

        const uint32_t stg = sb + buf * STAGEB;
#pragma unroll
        for (int ks = 0; ks < 32; ks += 16) {
            uint32_t bh[2][4], bl[2][4];
#pragma unroll
            for (int p = 0; p < 2; p++) {
                uint32_t off = ((bRow + p * 16) * TSTR + ks + bCol) * 2;
                ldsm4(bh[p], stg + TILEB + off);
                ldsm4(bl[p], stg + 2 * TILEB + off);
            }
#pragma unroll
            for (int mt = 0; mt < 4; mt++) {
                uint32_t ah[4];
                uint32_t off = ((aRow + mt * 16) * TSTR + ks + aCol) * 2;
                ldsm4(ah, stg + off);
#pragma unroll
                for (int nt = 0; nt < 4; nt++) {
                    uint32_t b0h = bh[nt >> 1][(nt & 1) * 2];
                    uint32_t b1h = bh[nt >> 1][(nt & 1) * 2 + 1];
                    uint32_t b0l = bl[nt >> 1][(nt & 1) * 2];
                    uint32_t b1l = bl[nt >> 1][(nt & 1) * 2 + 1];
                    mma_fp16(acc[mt][nt], ah, b0h, b1h);
                    mma_fp16(acc[mt][nt], ah, b0l, b1l);
                }
            }
        }
        buf = (buf + 1 == 3) ? 0 : buf + 1;
    }

#pragma unroll
    for (int mt = 0; mt < 4; mt++) {
        const int row0 = bm + wm * 64 + mt * 16 + (lane >> 2);
#pragma unroll
        for (int nt = 0; nt < 4; nt++) {
            const int col = bn + wn * 32 + nt * 8 + (lane & 3) * 2;
            float2 bv = *(const float2*)&bias[col];
            float v0 = (acc[mt][nt][0] + bv.x) * scale;
            float v1 = (acc[mt][nt][1] + bv.y) * scale;
            float v2 = (acc[mt][nt][2] + bv.x) * scale;
            float v3 = (acc[mt][nt][3] + bv.y) * scale;
            if (Cf) {
                *(float2*)&Cf[(size_t)row0 * N + col]       = make_float2(v0, v1);
                *(float2*)&Cf[(size_t)(row0 + 8) * N + col] = make_float2(v2, v3);
            } else if (Cq) {
                __half2 h0 = __floats2half2_rn(v0, v1);
                __half2 h1 = __floats2half2_rn(v2, v3);
                *(__half2*)&Cq[(size_t)row0 * N + col]       = h0;
                *(__half2*)&Cq[(size_t)(row0 + 8) * N + col] = h1;
            } else {
                uint32_t l0, l1;
                uint32_t h0 = packsplit16(v0, v1, l0);
                uint32_t h1 = packsplit16(v2, v3, l1);
                *(uint32_t*)&Ch[(size_t)row0 * N + col]       = h0;
                *(uint32_t*)&Cl[(size_t)row0 * N + col]       = l0;
                *(uint32_t*)&Ch[(size_t)(row0 + 8) * N + col] = h1;
                *(uint32_t*)&Cl[(size_t)(row0 + 8) * N + col] = l1;
            }
        }
    }
}

__global__ __launch_bounds__(256, 2)
void gemm_mma(const __half* __restrict__ A,
              const __half* __restrict__ Bh, const __half* __restrict__ Bl,
              const float* __restrict__ bias, float* __restrict__ Cf,
              __half* __restrict__ Ch, __half* __restrict__ Cl,
              __half* __restrict__ Cq, float scale, int N, int K)
{
    extern __shared__ char smem[];
    gemm_body(A, Bh, Bl, bias, Cf, Ch, Cl, Cq, scale, N, K, smem);
}

// Fused K+V projection (z selects set), fp16-split outputs.
__global__ __launch_bounds__(256, 2)
void gemm_mma_kv(const __half* __restrict__ A,
                 const __half* __restrict__ Wkh, const __half* __restrict__ Wkl,
                 const float* __restrict__ bk,
                 __half* __restrict__ Kh, __half* __restrict__ Kl,
                 const __half* __restrict__ Wvh, const __half* __restrict__ Wvl,
                 const float* __restrict__ bv,
                 __half* __restrict__ Vh, __half* __restrict__ Vl,
                 int N, int K)
{
    extern __shared__ char smem[];
    if (blockIdx.z == 0)
        gemm_body(A, Wkh, Wkl, bk, nullptr, Kh, Kl, nullptr, 1.0f, N, K, smem);
    else
        gemm_body(A, Wvh, Wvl, bv, nullptr, Vh, Vl, nullptr, 1.0f, N, K, smem);
}

// ---------------------------------------------------------------------------
// HMMA flash attention (round-14 proven, unchanged): Q single fp16,
// K/V split fp16, 2-stage KV pipeline, occ 2.
// ---------------------------------------------------------------------------
#define AST   72
#define TBQ   (128 * AST * 2)          // 18432 B
#define TBK   (64 * AST * 2)           // 9216 B
#define STG   (4 * TBK)                // 36864 B
#define ASMEM (TBQ + 2 * STG)          // 92160 B
#define KVT   64
#define NKV   (S_ / KVT)               // 32

__device__ __forceinline__ void load_kv(
    uint32_t dst, const __half* kh, const __half* kl,
    const __half* vh, const __half* vl, int kt, int tid)
{
    const int r  = tid >> 2;
    const int s0 = (tid & 3) * 2;
    const uint32_t so = (uint32_t)(r * (AST * 2) + s0 * 16);
    const size_t gi = (size_t)(kt * KVT + r) * DE + s0 * 8;
#pragma unroll
    for (int i = 0; i < 2; i++) {
        cp16(dst +           so + i * 16, kh + gi + i * 8);
        cp16(dst + TBK +     so + i * 16, kl + gi + i * 8);
        cp16(dst + 2 * TBK + so + i * 16, vh + gi + i * 8);
        cp16(dst + 3 * TBK + so + i * 16, vl + gi + i * 8);
    }
    asm volatile("cp.async.commit_group;" ::: "memory");
}

__global__ __launch_bounds__(256, 2)
void attn_mma(const __half* __restrict__ Qf_,
              const __half* __restrict__ Kh_, const __half* __restrict__ Kl_,
              const __half* __restrict__ Vh_, const __half* __restrict__ Vl_,
              __half* __restrict__ Of_)
{
    extern __shared__ char smem[];
    const uint32_t sb = s2u(smem);
    const uint32_t sQ = sb;
    const int tid  = threadIdx.x;
    const int lane = tid & 31;
    const int wid  = tid >> 5;
    const int b  = blockIdx.y >> 4;
    const int h  = blockIdx.y & 15;
    const int q0 = blockIdx.x * 128;

    const size_t headoff = (size_t)(b * S_) * DE + h * 64;
    const __half* qf = Qf_ + headoff + (size_t)q0 * DE;
    const __half* kh = Kh_ + headoff;
    const __half* kl = Kl_ + headoff;
    const __half* vh = Vh_ + headoff;
    const __half* vl = Vl_ + headoff;

    {
        const int r  = tid >> 1;
        const int s0 = (tid & 1) * 4;
        const uint32_t so = (uint32_t)(r * (AST * 2) + s0 * 16);
        const size_t gi = (size_t)r * DE + s0 * 8;
#pragma unroll
        for (int i = 0; i < 4; i++)
            cp16(sQ + so + i * 16, qf + gi + i * 8);
        asm volatile("cp.async.commit_group;" ::: "memory");
    }
    load_kv(sb + TBQ, kh, kl, vh, vl, 0, tid);
    asm volatile("cp.async.wait_group 0;" ::: "memory");
    __syncthreads();

    uint32_t qfr[4][4];
    {
        const uint32_t aRow = (uint32_t)(wid * 16 + (lane & 15));
        const uint32_t aCol = (uint32_t)(8 * (lane >> 4));
#pragma unroll
        for (int ks = 0; ks < 4; ks++) {
            uint32_t off = (aRow * AST + ks * 16 + aCol) * 2;
            ldsm4(qfr[ks], sQ + off);
        }
    }

    float mi[2] = {-1e30f, -1e30f}, li[2] = {0.0f, 0.0f};
    float o[8][4];
#pragma unroll
    for (int j = 0; j < 8; j++)
#pragma unroll
        for (int q = 0; q < 4; q++) o[j][q] = 0.0f;

    const uint32_t bRowK = (uint32_t)((lane & 7) + 8 * (lane >> 4));
    const uint32_t bColK = (uint32_t)(8 * ((lane >> 3) & 1));
    const uint32_t vRowB = (uint32_t)((lane & 7) + 8 * ((lane >> 3) & 1));
    const uint32_t vColB = (uint32_t)(8 * (lane >> 4));

    for (int kt = 0; kt < NKV; kt++) {
        if (kt + 1 < NKV)
            load_kv(sb + TBQ + ((kt + 1) & 1) * STG, kh, kl, vh, vl, kt + 1, tid);
        const uint32_t kb = sb + TBQ + (kt & 1) * STG;

        float s[8][4];
#pragma unroll
        for (int j = 0; j < 8; j++)
#pragma unroll
            for (int q = 0; q < 4; q++) s[j][q] = 0.0f;

#pragma unroll
        for (int ks = 0; ks < 4; ks++) {
#pragma unroll
            for (int ng = 0; ng < 4; ng++) {
                uint32_t kfh[4], kfl[4];
                uint32_t off = ((ng * 16 + bRowK) * AST + ks * 16 + bColK) * 2;
                ldsm4(kfh, kb + off);
                ldsm4(kfl, kb + TBK + off);
                mma_fp16(s[2 * ng],     qfr[ks], kfh[0], kfh[1]);
                mma_fp16(s[2 * ng + 1], qfr[ks], kfh[2], kfh[3]);
                mma_fp16(s[2 * ng],     qfr[ks], kfl[0], kfl[1]);
                mma_fp16(s[2 * ng + 1], qfr[ks], kfl[2], kfl[3]);
            }
        }

        float mn0 = -1e30f, mn1 = -1e30f;
#pragma unroll
        for (int j = 0; j < 8; j++) {
            mn0 = fmaxf(mn0, fmaxf(s[j][0], s[j][1]));
            mn1 = fmaxf(mn1, fmaxf(s[j][2], s[j][3]));
        }
        mn0 = fmaxf(mn0, __shfl_xor_sync(0xffffffffu, mn0, 1));
        mn0 = fmaxf(mn0, __shfl_xor_sync(0xffffffffu, mn0, 2));
        mn1 = fmaxf(mn1, __shfl_xor_sync(0xffffffffu, mn1, 1));
        mn1 = fmaxf(mn1, __shfl_xor_sync(0xffffffffu, mn1, 2));
        const float m0 = fmaxf(mi[0], mn0), m1 = fmaxf(mi[1], mn1);
        const float c0 = exp2f(mi[0] - m0), c1 = exp2f(mi[1] - m1);
        float rs0 = 0.0f, rs1 = 0.0f;
#pragma unroll
        for (int j = 0; j < 8; j++) {
            s[j][0] = exp2f(s[j][0] - m0); rs0 += s[j][0];
            s[j][1] = exp2f(s[j][1] - m0); rs0 += s[j][1];
            s[j][2] = exp2f(s[j][2] - m1); rs1 += s[j][2];
            s[j][3] = exp2f(s[j][3] - m1); rs1 += s[j][3];
        }
        rs0 += __shfl_xor_sync(0xffffffffu, rs0, 1);
        rs0 += __shfl_xor_sync(0xffffffffu, rs0, 2);
        rs1 += __shfl_xor_sync(0xffffffffu, rs1, 1);
        rs1 += __shfl_xor_sync(0xffffffffu, rs1, 2);
        li[0] = li[0] * c0 + rs0;  mi[0] = m0;
        li[1] = li[1] * c1 + rs1;  mi[1] = m1;
#pragma unroll
        for (int j = 0; j < 8; j++) {
            o[j][0] *= c0; o[j][1] *= c0;
            o[j][2] *= c1; o[j][3] *= c1;
        }

        const uint32_t vb = kb + 2 * TBK;
#pragma unroll
        for (int j2 = 0; j2 < 4; j2++) {
            uint32_t pa[4];
            __half2 p0 = __floats2half2_rn(s[2 * j2][0],     s[2 * j2][1]);
            __half2 p1 = __floats2half2_rn(s[2 * j2][2],     s[2 * j2][3]);
            __half2 p2 = __floats2half2_rn(s[2 * j2 + 1][0], s[2 * j2 + 1][1]);
            __half2 p3 = __floats2half2_rn(s[2 * j2 + 1][2], s[2 * j2 + 1][3]);
            pa[0] = *(uint32_t*)&p0;
            pa[1] = *(uint32_t*)&p1;
            pa[2] = *(uint32_t*)&p2;
            pa[3] = *(uint32_t*)&p3;
#pragma unroll
            for (int ng = 0; ng < 4; ng++) {
                uint32_t vfh[4], vfl[4];
                uint32_t off = ((j2 * 16 + vRowB) * AST + ng * 16 + vColB) * 2;
                ldsm4t(vfh, vb + off);
                ldsm4t(vfl, vb + TBK + off);
                const int n0 = ng * 2;
                mma_fp16(o[n0],     pa, vfh[0], vfh[1]);
                mma_fp16(o[n0 + 1], pa, vfh[2], vfh[3]);
                mma_fp16(o[n0],     pa, vfl[0], vfl[1]);
                mma_fp16(o[n0 + 1], pa, vfl[2], vfl[3]);
            }
        }

        if (kt + 1 < NKV)
            asm volatile("cp.async.wait_group 0;" ::: "memory");
        __syncthreads();
    }

    const float inv0 = 1.0f / li[0], inv1 = 1.0f / li[1];
    __half* of = Of_ + headoff + (size_t)q0 * DE;
    const int r0 = wid * 16 + (lane >> 2);
#pragma unroll
    for (int j = 0; j < 8; j++) {
        const int c = j * 8 + (lane & 3) * 2;
        __half2 h0 = __floats2half2_rn(o[j][0] * inv0, o[j][1] * inv0);
        __half2 h1 = __floats2half2_rn(o[j][2] * inv1, o[j][3] * inv1);
        *(__half2*)&of[(size_t)r0 * DE + c]       = h0;
        *(__half2*)&of[(size_t)(r0 + 8) * DE + c] = h1;
    }
}

// ---------------------------------------------------------------------------
extern "C" void kernel_launch(void* const* d_in, const int* in_sizes, int n_in,
                              void* d_out, int out_size)
{
    const float* x  = (const float*)d_in[0];
    const float* y  = (const float*)d_in[1];
    const float* Wq = (const float*)d_in[2];
    const float* bq = (const float*)d_in[3];
    const float* Wk = (const float*)d_in[4];
    const float* bk = (const float*)d_in[5];
    const float* Wv = (const float*)d_in[6];
    const float* bv = (const float*)d_in[7];
    const float* Wo = (const float*)d_in[8];
    const float* bo = (const float*)d_in[9];
    float* out = (float*)d_out;

    __half *xf, *yf, *of, *qF, *kH, *kL, *vH, *vL;
    __half *wqh, *wql, *wkh, *wkl, *wvh, *wvl, *woh, *wol;
    cudaGetSymbolAddress((void**)&xf, g_xf);
    cudaGetSymbolAddress((void**)&yf, g_yf);
    cudaGetSymbolAddress((void**)&of, g_of);
    cudaGetSymbolAddress((void**)&qF, g_Qf);
    cudaGetSymbolAddress((void**)&kH, g_Kh);   cudaGetSymbolAddress((void**)&kL, g_Kl);
    cudaGetSymbolAddress((void**)&vH, g_Vh);   cudaGetSymbolAddress((void**)&vL, g_Vl);
    cudaGetSymbolAddress((void**)&wqh, g_wqh); cudaGetSymbolAddress((void**)&wql, g_wql);
    cudaGetSymbolAddress((void**)&wkh, g_wkh); cudaGetSymbolAddress((void**)&wkl, g_wkl);
    cudaGetSymbolAddress((void**)&wvh, g_wvh); cudaGetSymbolAddress((void**)&wvl, g_wvl);
    cudaGetSymbolAddress((void**)&woh, g_woh); cudaGetSymbolAddress((void**)&wol, g_wol);

    cudaFuncSetAttribute(gemm_mma, cudaFuncAttributeMaxDynamicSharedMemorySize, GSMEM);
    cudaFuncSetAttribute(gemm_mma_kv, cudaFuncAttributeMaxDynamicSharedMemorySize, GSMEM);
    cudaFuncSetAttribute(attn_mma, cudaFuncAttributeMaxDynamicSharedMemorySize, ASMEM);

    dim3 blk(256);
    dim3 grid_g(DE / 128, M_ / 128);          // (8, 64)
    dim3 grid_kv(DE / 128, M_ / 128, 2);      // (8, 64, 2)
    dim3 grid_a(S_ / 128, B_ * NH);           // (16, 64)

    conv_f16<<<(M_ * DE / 4 + 255) / 256, blk>>>(x, xf, M_ * DE / 4);        // 1
    tsplit_w16<<<dim3(DE / 32, DE / 32), blk>>>(Wq, wqh, wql, DE, DE);       // 2
    conv_f16<<<(M_ * DC / 4 + 255) / 256, blk>>>(y, yf, M_ * DC / 4);        // 3

    // 4: PROFILED. Q -> single fp16, scale folds 1/sqrt(64)*log2(e).
    gemm_mma<<<grid_g, blk, GSMEM>>>(xf, wqh, wql, bq, nullptr,
                                     nullptr, nullptr, qF,
                                     0.125f * 1.4426950408889634f, DE, DE);

    tsplit_w16<<<dim3(DE / 32, DC / 32), blk>>>(Wk, wkh, wkl, DC, DE);       // 5
    tsplit_w16<<<dim3(DE / 32, DC / 32), blk>>>(Wv, wvh, wvl, DC, DE);       // 6
    tsplit_w16<<<dim3(DE / 32, DE / 32), blk>>>(Wo, woh, wol, DE, DE);       // 7

    // 8: fused K+V projections -> fp16 split
    gemm_mma_kv<<<grid_kv, blk, GSMEM>>>(yf, wkh, wkl, bk, kH, kL,
                                         wvh, wvl, bv, vH, vL, DE, DC);

    attn_mma<<<grid_a, blk, ASMEM>>>(qF, kH, kL, vH, vL, of);                // 9

    gemm_mma<<<grid_g, blk, GSMEM>>>(of, woh, wol, bo, out,
                                     nullptr, nullptr, nullptr, 1.0f, DE, DE); // 10
}

// round 16
// speedup vs baseline: 1.0225x; 1.0225x over previous
#include <cuda_runtime.h>
#include <cuda_bf16.h>
#include <cuda_fp16.h>
#include <cstdint>

#define B_  4
#define S_  2048
#define DE  1024
#define DC  768
#define NH  16
#define DH  64
#define M_  (B_ * S_)   // 8192

// ---------------- scratch (allocation-free) ----------------
__device__ __half g_xf[M_ * DE];
__device__ __half g_yf[M_ * DC];
__device__ __half g_of[M_ * DE];      // attention output (single fp16)
__device__ __half g_Qf[M_ * DE];
__device__ __half g_Kh[M_ * DE], g_Kl[M_ * DE];
__device__ __half g_Vh[M_ * DE], g_Vl[M_ * DE];
__device__ __half g_wqh[DE * DE], g_wql[DE * DE];
__device__ __half g_wkh[DE * DC], g_wkl[DE * DC];
__device__ __half g_wvh[DE * DC], g_wvl[DE * DC];
__device__ __half g_woh[DE * DE], g_wol[DE * DE];

// ---------------- helpers ----------------
__device__ __forceinline__ uint32_t s2u(const void* p) {
    uint32_t a;
    asm("{ .reg .u64 t; cvta.to.shared.u64 t, %1; cvt.u32.u64 %0, t; }"
        : "=r"(a) : "l"(p));
    return a;
}
__device__ __forceinline__ void cp16(uint32_t saddr, const void* g) {
    asm volatile("cp.async.cg.shared.global [%0], [%1], 16;" :: "r"(saddr), "l"(g));
}
__device__ __forceinline__ void ldsm4(uint32_t* r, uint32_t addr) {
    asm volatile("ldmatrix.sync.aligned.m8n8.x4.shared.b16 {%0,%1,%2,%3}, [%4];"
        : "=r"(r[0]), "=r"(r[1]), "=r"(r[2]), "=r"(r[3]) : "r"(addr));
}
__device__ __forceinline__ void ldsm4t(uint32_t* r, uint32_t addr) {
    asm volatile("ldmatrix.sync.aligned.m8n8.x4.trans.shared.b16 {%0,%1,%2,%3}, [%4];"
        : "=r"(r[0]), "=r"(r[1]), "=r"(r[2]), "=r"(r[3]) : "r"(addr));
}
__device__ __forceinline__ void mma_fp16(float* c, const uint32_t* a,
                                         uint32_t b0, uint32_t b1) {
    asm volatile(
        "mma.sync.aligned.m16n8k16.row.col.f32.f16.f16.f32 "
        "{%0,%1,%2,%3}, {%4,%5,%6,%7}, {%8,%9}, {%0,%1,%2,%3};"
        : "+f"(c[0]), "+f"(c[1]), "+f"(c[2]), "+f"(c[3])
        : "r"(a[0]), "r"(a[1]), "r"(a[2]), "r"(a[3]), "r"(b0), "r"(b1));
}
__device__ __forceinline__ uint32_t packsplit16(float a, float b, uint32_t& lo) {
    __half ha = __float2half_rn(a), hb = __float2half_rn(b);
    __half la = __float2half_rn(a - __half2float(ha));
    __half lb = __float2half_rn(b - __half2float(hb));
    __half2 H(ha, hb), L(la, lb);
    lo = *(uint32_t*)&L;
    return *(uint32_t*)&H;
}

// ---------------------------------------------------------------------------
__global__ __launch_bounds__(256)
void conv_f16(const float* __restrict__ in, __half* __restrict__ out, int n4)
{
    int i = blockIdx.x * 256 + threadIdx.x;
    if (i >= n4) return;
    float4 v = ((const float4*)in)[i];
    __half2 h0 = __floats2half2_rn(v.x, v.y);
    __half2 h1 = __floats2half2_rn(v.z, v.w);
    ((__half2*)out)[i * 2 + 0] = h0;
    ((__half2*)out)[i * 2 + 1] = h1;
}

// ---------------------------------------------------------------------------
// Fused transpose+split for all four weights. blockIdx.z selects the weight.
// W[K,N] f32 -> Wt_hi/Wt_lo [N,K] fp16.  (N = DE for all; K in {DE,DC}.)
// ---------------------------------------------------------------------------
__global__ __launch_bounds__(256)
void tsplit_all(const float* __restrict__ Wq, const float* __restrict__ Wk,
                const float* __restrict__ Wv, const float* __restrict__ Wo,
                __half* __restrict__ qh, __half* __restrict__ ql,
                __half* __restrict__ kh, __half* __restrict__ kl,
                __half* __restrict__ vh, __half* __restrict__ vl,
                __half* __restrict__ oh, __half* __restrict__ ol)
{
    const int z = blockIdx.z;
    const float* W; __half* hi; __half* lo; int K;
    if      (z == 0) { W = Wq; hi = qh; lo = ql; K = DE; }
    else if (z == 1) { W = Wk; hi = kh; lo = kl; K = DC; }
    else if (z == 2) { W = Wv; hi = vh; lo = vl; K = DC; }
    else             { W = Wo; hi = oh; lo = ol; K = DE; }

    const int k0 = blockIdx.y * 32;
    if (k0 >= K) return;
    const int n0 = blockIdx.x * 32;

    __shared__ float t[32][33];
    int tx = threadIdx.x & 31, ty = threadIdx.x >> 5;
#pragma unroll
    for (int j = 0; j < 32; j += 8)
        t[ty + j][tx] = W[(size_t)(k0 + ty + j) * DE + n0 + tx];
    __syncthreads();
#pragma unroll
    for (int j = 0; j < 32; j += 8) {
        float v = t[tx][ty + j];
        __half h = __float2half_rn(v);
        size_t o = (size_t)(n0 + ty + j) * K + k0 + tx;
        hi[o] = h;
        lo[o] = __float2half_rn(v - __half2float(h));
    }
}

// ---------------------------------------------------------------------------
// fp16 one-sided-split HMMA GEMM, proven round-14 shape:
// 128x128 tile, BK=32, 2 CTA/SM, 2-stage cp.async, 80B rows, 2 MMAs per k16.
// ---------------------------------------------------------------------------
#define TSTR   40
#define TILEB  (128 * TSTR * 2)        // 10240 B
#define STAGEB (3 * TILEB)             // 30720 B (A, Bh, Bl)
#define GSMEM  (2 * STAGEB)            // 61440 B

__device__ __forceinline__ void load_stage(
    uint32_t stb, const __half* A, const __half* Bh, const __half* Bl,
    int bm, int bn, int k0, int K, int tid)
{
    const int r  = tid >> 1;
    const int s0 = (tid & 1) * 2;
    const uint32_t so = (uint32_t)(r * (TSTR * 2) + s0 * 16);
    const size_t ga = (size_t)(bm + r) * K + k0 + s0 * 8;
    const size_t gb = (size_t)(bn + r) * K + k0 + s0 * 8;
    cp16(stb + so,                  A  + ga);
    cp16(stb + so + 16,             A  + ga + 8);
    cp16(stb + TILEB + so,          Bh + gb);
    cp16(stb + TILEB + so + 16,     Bh + gb + 8);
    cp16(stb + 2 * TILEB + so,      Bl + gb);
    cp16(stb + 2 * TILEB + so + 16, Bl + gb + 8);
    asm volatile("cp.async.commit_group;" ::: "memory");
}

__device__ __forceinline__ void gemm_body(
    const __half* __restrict__ A,
    const __half* __restrict__ Bh, const __half* __restrict__ Bl,
    const float* __restrict__ bias, float* __restrict__ Cf,
    __half* __restrict__ Ch, __half* __restrict__ Cl, __half* __restrict__ Cq,
    float scale, int N, int K, char* smem)
{
    const uint32_t sb = s2u(smem);
    const int tid  = threadIdx.x;
    const int lane = tid & 31;
    const int wid  = tid >> 5;
    const int wm   = wid >> 2;
    const int wn   = wid & 3;
    const int bm = blockIdx.y * 128, bn = blockIdx.x * 128;
    const int NC = K / 32;

    float acc[4][4][4];
#pragma unroll
    for (int i = 0; i < 4; i++)
#pragma unroll
        for (int j = 0; j < 4; j++)
#pragma unroll
            for (int q = 0; q < 4; q++) acc[i][j][q] = 0.0f;

    const uint32_t aRow = (uint32_t)(wm * 64 + (lane & 15));
    const uint32_t aCol = (uint32_t)(8 * (lane >> 4));
    const uint32_t bRow = (uint32_t)(wn * 32 + (lane & 7) + 8 * (lane >> 4));
    const uint32_t bCol = (uint32_t)(8 * ((lane >> 3) & 1));

    load_stage(sb, A, Bh, Bl, bm, bn, 0, K, tid);

    for (int c = 0; c < NC; c++) {
        asm volatile("cp.async.wait_group 0;" ::: "memory");
        __syncthreads();
        if (c + 1 < NC)
            load_stage(sb + ((c + 1) & 1) * STAGEB, A, Bh, Bl,
                       bm, bn, (c + 1) * 32, K, tid);

        const uint32_t stg = sb + (c & 1) * STAGEB;
#pragma unroll
        for (int ks = 0; ks < 32; ks += 16) {
            uint32_t bh[2][4], bl[2][4];
#pragma unroll
            for (int p = 0; p < 2; p++) {
                uint32_t off = ((bRow + p * 16) * TSTR + ks + bCol) * 2;
                ldsm4(bh[p], stg + TILEB + off);
                ldsm4(bl[p], stg + 2 * TILEB + off);
            }
#pragma unroll
            for (int mt = 0; mt < 4; mt++) {
                uint32_t ah[4];
                uint32_t off = ((aRow + mt * 16) * TSTR + ks + aCol) * 2;
                ldsm4(ah, stg + off);
#pragma unroll
                for (int nt = 0; nt < 4; nt++) {
                    uint32_t b0h = bh[nt >> 1][(nt & 1) * 2];
                    uint32_t b1h = bh[nt >> 1][(nt & 1) * 2 + 1];
                    uint32_t b0l = bl[nt >> 1][(nt & 1) * 2];
                    uint32_t b1l = bl[nt >> 1][(nt & 1) * 2 + 1];
                    mma_fp16(acc[mt][nt], ah, b0h, b1h);
                    mma_fp16(acc[mt][nt], ah, b0l, b1l);
                }
            }
        }
    }

#pragma unroll
    for (int mt = 0; mt < 4; mt++) {
        const int row0 = bm + wm * 64 + mt * 16 + (lane >> 2);
#pragma unroll
        for (int nt = 0; nt < 4; nt++) {
            const int col = bn + wn * 32 + nt * 8 + (lane & 3) * 2;
            float2 bv = *(const float2*)&bias[col];
            float v0 = (acc[mt][nt][0] + bv.x) * scale;
            float v1 = (acc[mt][nt][1] + bv.y) * scale;
            float v2 = (acc[mt][nt][2] + bv.x) * scale;
            float v3 = (acc[mt][nt][3] + bv.y) * scale;
            if (Cf) {
                *(float2*)&Cf[(size_t)row0 * N + col]       = make_float2(v0, v1);
                *(float2*)&Cf[(size_t)(row0 + 8) * N + col] = make_float2(v2, v3);
            } else if (Cq) {
                __half2 h0 = __floats2half2_rn(v0, v1);
                __half2 h1 = __floats2half2_rn(v2, v3);
                *(__half2*)&Cq[(size_t)row0 * N + col]       = h0;
                *(__half2*)&Cq[(size_t)(row0 + 8) * N + col] = h1;
            } else {
                uint32_t l0, l1;
                uint32_t h0 = packsplit16(v0, v1, l0);
                uint32_t h1 = packsplit16(v2, v3, l1);
                *(uint32_t*)&Ch[(size_t)row0 * N + col]       = h0;
                *(uint32_t*)&Cl[(size_t)row0 * N + col]       = l0;
                *(uint32_t*)&Ch[(size_t)(row0 + 8) * N + col] = h1;
                *(uint32_t*)&Cl[(size_t)(row0 + 8) * N + col] = l1;
            }
        }
    }
}

// Fused Q+K+V projection: z=0 -> Q (xf, single out, scaled); z=1 -> K; z=2 -> V.
__global__ __launch_bounds__(256, 2)
void gemm_qkv(const __half* __restrict__ xf, const __half* __restrict__ yf,
              const __half* __restrict__ wqh, const __half* __restrict__ wql,
              const float* __restrict__ bq, __half* __restrict__ Qf,
              const __half* __restrict__ wkh, const __half* __restrict__ wkl,
              const float* __restrict__ bk,
              __half* __restrict__ Kh, __half* __restrict__ Kl,
              const __half* __restrict__ wvh, const __half* __restrict__ wvl,
              const float* __restrict__ bv,
              __half* __restrict__ Vh, __half* __restrict__ Vl,
              float qscale)
{
    extern __shared__ char smem[];
    const int z = blockIdx.z;
    if (z == 0)
        gemm_body(xf, wqh, wql, bq, nullptr, nullptr, nullptr, Qf, qscale, DE, DE, smem);
    else if (z == 1)
        gemm_body(yf, wkh, wkl, bk, nullptr, Kh, Kl, nullptr, 1.0f, DE, DC, smem);
    else
        gemm_body(yf, wvh, wvl, bv, nullptr, Vh, Vl, nullptr, 1.0f, DE, DC, smem);
}

// Output projection (fp32 out).
__global__ __launch_bounds__(256, 2)
void gemm_mma(const __half* __restrict__ A,
              const __half* __restrict__ Bh, const __half* __restrict__ Bl,
              const float* __restrict__ bias, float* __restrict__ Cf,
              float scale, int N, int K)
{
    extern __shared__ char smem[];
    gemm_body(A, Bh, Bl, bias, Cf, nullptr, nullptr, nullptr, scale, N, K, smem);
}

// ---------------------------------------------------------------------------
// HMMA flash attention (round-14 proven, unchanged).
// ---------------------------------------------------------------------------
#define AST   72
#define TBQ   (128 * AST * 2)          // 18432 B
#define TBK   (64 * AST * 2)           // 9216 B
#define STG   (4 * TBK)                // 36864 B
#define ASMEM (TBQ + 2 * STG)          // 92160 B
#define KVT   64
#define NKV   (S_ / KVT)               // 32

__device__ __forceinline__ void load_kv(
    uint32_t dst, const __half* kh, const __half* kl,
    const __half* vh, const __half* vl, int kt, int tid)
{
    const int r  = tid >> 2;
    const int s0 = (tid & 3) * 2;
    const uint32_t so = (uint32_t)(r * (AST * 2) + s0 * 16);
    const size_t gi = (size_t)(kt * KVT + r) * DE + s0 * 8;
#pragma unroll
    for (int i = 0; i < 2; i++) {
        cp16(dst +           so + i * 16, kh + gi + i * 8);
        cp16(dst + TBK +     so + i * 16, kl + gi + i * 8);
        cp16(dst + 2 * TBK + so + i * 16, vh + gi + i * 8);
        cp16(dst + 3 * TBK + so + i * 16, vl + gi + i * 8);
    }
    asm volatile("cp.async.commit_group;" ::: "memory");
}

__global__ __launch_bounds__(256, 2)
void attn_mma(const __half* __restrict__ Qf_,
              const __half* __restrict__ Kh_, const __half* __restrict__ Kl_,
              const __half* __restrict__ Vh_, const __half* __restrict__ Vl_,
              __half* __restrict__ Of_)
{
    extern __shared__ char smem[];
    const uint32_t sb = s2u(smem);
    const uint32_t sQ = sb;
    const int tid  = threadIdx.x;
    const int lane = tid & 31;
    const int wid  = tid >> 5;
    const int b  = blockIdx.y >> 4;
    const int h  = blockIdx.y & 15;
    const int q0 = blockIdx.x * 128;

    const size_t headoff = (size_t)(b * S_) * DE + h * 64;
    const __half* qf = Qf_ + headoff + (size_t)q0 * DE;
    const __half* kh = Kh_ + headoff;
    const __half* kl = Kl_ + headoff;
    const __half* vh = Vh_ + headoff;
    const __half* vl = Vl_ + headoff;

    {
        const int r  = tid >> 1;
        const int s0 = (tid & 1) * 4;
        const uint32_t so = (uint32_t)(r * (AST * 2) + s0 * 16);
        const size_t gi = (size_t)r * DE + s0 * 8;
#pragma unroll
        for (int i = 0; i < 4; i++)
            cp16(sQ + so + i * 16, qf + gi + i * 8);
        asm volatile("cp.async.commit_group;" ::: "memory");
    }
    load_kv(sb + TBQ, kh, kl, vh, vl, 0, tid);
    asm volatile("cp.async.wait_group 0;" ::: "memory");
    __syncthreads();

    uint32_t qfr[4][4];
    {
        const uint32_t aRow = (uint32_t)(wid * 16 + (lane & 15));
        const uint32_t aCol = (uint32_t)(8 * (lane >> 4));
#pragma unroll
        for (int ks = 0; ks < 4; ks++) {
            uint32_t off = (aRow * AST + ks * 16 + aCol) * 2;
            ldsm4(qfr[ks], sQ + off);
        }
    }

    float mi[2] = {-1e30f, -1e30f}, li[2] = {0.0f, 0.0f};
    float o[8][4];
#pragma unroll
    for (int j = 0; j < 8; j++)
#pragma unroll
        for (int q = 0; q < 4; q++) o[j][q] = 0.0f;

    const uint32_t bRowK = (uint32_t)((lane & 7) + 8 * (lane >> 4));
    const uint32_t bColK = (uint32_t)(8 * ((lane >> 3) & 1));
    const uint32_t vRowB = (uint32_t)((lane & 7) + 8 * ((lane >> 3) & 1));
    const uint32_t vColB = (uint32_t)(8 * (lane >> 4));

    for (int kt = 0; kt < NKV; kt++) {
        if (kt + 1 < NKV)
            load_kv(sb + TBQ + ((kt + 1) & 1) * STG, kh, kl, vh, vl, kt + 1, tid);
        const uint32_t kb = sb + TBQ + (kt & 1) * STG;

        float s[8][4];
#pragma unroll
        for (int j = 0; j < 8; j++)
#pragma unroll
            for (int q = 0; q < 4; q++) s[j][q] = 0.0f;

#pragma unroll
        for (int ks = 0; ks < 4; ks++) {
#pragma unroll
            for (int ng = 0; ng < 4; ng++) {
                uint32_t kfh[4], kfl[4];
                uint32_t off = ((ng * 16 + bRowK) * AST + ks * 16 + bColK) * 2;
                ldsm4(kfh, kb + off);
                ldsm4(kfl, kb + TBK + off);
                mma_fp16(s[2 * ng],     qfr[ks], kfh[0], kfh[1]);
                mma_fp16(s[2 * ng + 1], qfr[ks], kfh[2], kfh[3]);
                mma_fp16(s[2 * ng],     qfr[ks], kfl[0], kfl[1]);
                mma_fp16(s[2 * ng + 1], qfr[ks], kfl[2], kfl[3]);
            }
        }

        float mn0 = -1e30f, mn1 = -1e30f;
#pragma unroll
        for (int j = 0; j < 8; j++) {
            mn0 = fmaxf(mn0, fmaxf(s[j][0], s[j][1]));
            mn1 = fmaxf(mn1, fmaxf(s[j][2], s[j][3]));
        }
        mn0 = fmaxf(mn0, __shfl_xor_sync(0xffffffffu, mn0, 1));
        mn0 = fmaxf(mn0, __shfl_xor_sync(0xffffffffu, mn0, 2));
        mn1 = fmaxf(mn1, __shfl_xor_sync(0xffffffffu, mn1, 1));
        mn1 = fmaxf(mn1, __shfl_xor_sync(0xffffffffu, mn1, 2));
        const float m0 = fmaxf(mi[0], mn0), m1 = fmaxf(mi[1], mn1);
        const float c0 = exp2f(mi[0] - m0), c1 = exp2f(mi[1] - m1);
        float rs0 = 0.0f, rs1 = 0.0f;
#pragma unroll
        for (int j = 0; j < 8; j++) {
            s[j][0] = exp2f(s[j][0] - m0); rs0 += s[j][0];
            s[j][1] = exp2f(s[j][1] - m0); rs0 += s[j][1];
            s[j][2] = exp2f(s[j][2] - m1); rs1 += s[j][2];
            s[j][3] = exp2f(s[j][3] - m1); rs1 += s[j][3];
        }
        rs0 += __shfl_xor_sync(0xffffffffu, rs0, 1);
        rs0 += __shfl_xor_sync(0xffffffffu, rs0, 2);
        rs1 += __shfl_xor_sync(0xffffffffu, rs1, 1);
        rs1 += __shfl_xor_sync(0xffffffffu, rs1, 2);
        li[0] = li[0] * c0 + rs0;  mi[0] = m0;
        li[1] = li[1] * c1 + rs1;  mi[1] = m1;
#pragma unroll
        for (int j = 0; j < 8; j++) {
            o[j][0] *= c0; o[j][1] *= c0;
            o[j][2] *= c1; o[j][3] *= c1;
        }

        const uint32_t vb = kb + 2 * TBK;
#pragma unroll
        for (int j2 = 0; j2 < 4; j2++) {
            uint32_t pa[4];
            __half2 p0 = __floats2half2_rn(s[2 * j2][0],     s[2 * j2][1]);
            __half2 p1 = __floats2half2_rn(s[2 * j2][2],     s[2 * j2][3]);
            __half2 p2 = __floats2half2_rn(s[2 * j2 + 1][0], s[2 * j2 + 1][1]);
            __half2 p3 = __floats2half2_rn(s[2 * j2 + 1][2], s[2 * j2 + 1][3]);
            pa[0] = *(uint32_t*)&p0;
            pa[1] = *(uint32_t*)&p1;
            pa[2] = *(uint32_t*)&p2;
            pa[3] = *(uint32_t*)&p3;
#pragma unroll
            for (int ng = 0; ng < 4; ng++) {
                uint32_t vfh[4], vfl[4];
                uint32_t off = ((j2 * 16 + vRowB) * AST + ng * 16 + vColB) * 2;
                ldsm4t(vfh, vb + off);
                ldsm4t(vfl, vb + TBK + off);
                const int n0 = ng * 2;
                mma_fp16(o[n0],     pa, vfh[0], vfh[1]);
                mma_fp16(o[n0 + 1], pa, vfh[2], vfh[3]);
                mma_fp16(o[n0],     pa, vfl[0], vfl[1]);
                mma_fp16(o[n0 + 1], pa, vfl[2], vfl[3]);
            }
        }

        if (kt + 1 < NKV)
            asm volatile("cp.async.wait_group 0;" ::: "memory");
        __syncthreads();
    }

    const float inv0 = 1.0f / li[0], inv1 = 1.0f / li[1];
    __half* of = Of_ + headoff + (size_t)q0 * DE;
    const int r0 = wid * 16 + (lane >> 2);
#pragma unroll
    for (int j = 0; j < 8; j++) {
        const int c = j * 8 + (lane & 3) * 2;
        __half2 h0 = __floats2half2_rn(o[j][0] * inv0, o[j][1] * inv0);
        __half2 h1 = __floats2half2_rn(o[j][2] * inv1, o[j][3] * inv1);
        *(__half2*)&of[(size_t)r0 * DE + c]       = h0;
        *(__half2*)&of[(size_t)(r0 + 8) * DE + c] = h1;
    }
}

// ---------------------------------------------------------------------------
extern "C" void kernel_launch(void* const* d_in, const int* in_sizes, int n_in,
                              void* d_out, int out_size)
{
    const float* x  = (const float*)d_in[0];
    const float* y  = (const float*)d_in[1];
    const float* Wq = (const float*)d_in[2];
    const float* bq = (const float*)d_in[3];
    const float* Wk = (const float*)d_in[4];
    const float* bk = (const float*)d_in[5];
    const float* Wv = (const float*)d_in[6];
    const float* bv = (const float*)d_in[7];
    const float* Wo = (const float*)d_in[8];
    const float* bo = (const float*)d_in[9];
    float* out = (float*)d_out;

    __half *xf, *yf, *of, *qF, *kH, *kL, *vH, *vL;
    __half *wqh, *wql, *wkh, *wkl, *wvh, *wvl, *woh, *wol;
    cudaGetSymbolAddress((void**)&xf, g_xf);
    cudaGetSymbolAddress((void**)&yf, g_yf);
    cudaGetSymbolAddress((void**)&of, g_of);
    cudaGetSymbolAddress((void**)&qF, g_Qf);
    cudaGetSymbolAddress((void**)&kH, g_Kh);   cudaGetSymbolAddress((void**)&kL, g_Kl);
    cudaGetSymbolAddress((void**)&vH, g_Vh);   cudaGetSymbolAddress((void**)&vL, g_Vl);
    cudaGetSymbolAddress((void**)&wqh, g_wqh); cudaGetSymbolAddress((void**)&wql, g_wql);
    cudaGetSymbolAddress((void**)&wkh, g_wkh); cudaGetSymbolAddress((void**)&wkl, g_wkl);
    cudaGetSymbolAddress((void**)&wvh, g_wvh); cudaGetSymbolAddress((void**)&wvl, g_wvl);
    cudaGetSymbolAddress((void**)&woh, g_woh); cudaGetSymbolAddress((void**)&wol, g_wol);

    cudaFuncSetAttribute(gemm_qkv, cudaFuncAttributeMaxDynamicSharedMemorySize, GSMEM);
    cudaFuncSetAttribute(gemm_mma, cudaFuncAttributeMaxDynamicSharedMemorySize, GSMEM);
    cudaFuncSetAttribute(attn_mma, cudaFuncAttributeMaxDynamicSharedMemorySize, ASMEM);

    dim3 blk(256);
    dim3 grid_qkv(DE / 128, M_ / 128, 3);     // (8, 64, 3) = 1536 CTAs
    dim3 grid_g(DE / 128, M_ / 128);          // (8, 64)
    dim3 grid_a(S_ / 128, B_ * NH);           // (16, 64)

    conv_f16<<<(M_ * DE / 4 + 255) / 256, blk>>>(x, xf, M_ * DE / 4);        // 1
    tsplit_all<<<dim3(DE / 32, DE / 32, 4), blk>>>(Wq, Wk, Wv, Wo,
                                                   wqh, wql, wkh, wkl,
                                                   wvh, wvl, woh, wol);      // 2
    conv_f16<<<(M_ * DC / 4 + 255) / 256, blk>>>(y, yf, M_ * DC / 4);        // 3

    // 4: PROFILED. Fused Q+K+V projections.
    gemm_qkv<<<grid_qkv, blk, GSMEM>>>(xf, yf,
                                       wqh, wql, bq, qF,
                                       wkh, wkl, bk, kH, kL,
                                       wvh, wvl, bv, vH, vL,
                                       0.125f * 1.4426950408889634f);

    attn_mma<<<grid_a, blk, ASMEM>>>(qF, kH, kL, vH, vL, of);                // 5

    gemm_mma<<<grid_g, blk, GSMEM>>>(of, woh, wol, bo, out, 1.0f, DE, DE);   // 6
}